// round 1
// baseline (speedup 1.0000x reference)
#include <cuda_runtime.h>

#define HIDN 256
#define EDIM 64
#define KIN  577        // 2*HID + 1 + EDGE_DIM
#define TE   32         // edges (or nodes) per CTA
#define NTHREADS 256
#define PITCH 33        // smem row pitch (conflict-free)
#define MAXN 50000

// scratch: per-node aggregated messages m_i  (50000 * 256 floats = 51.2 MB)
__device__ float g_mi[(size_t)MAXN * HIDN];

__device__ __forceinline__ float silu_f(float v) {
    return v * (1.0f / (1.0f + __expf(-v)));
}

// ---------------------------------------------------------------------------
// init: zero m_i accumulator, seed x_out region of d_out with x
// ---------------------------------------------------------------------------
__global__ void init_kernel(const float* __restrict__ x,
                            float* __restrict__ mi,
                            float* __restrict__ xout,
                            int total_mi, int total_x)
{
    int i = blockIdx.x * blockDim.x + threadIdx.x;
    if (i < total_mi) mi[i] = 0.0f;
    if (i < total_x)  xout[i] = x[i];
}

// ---------------------------------------------------------------------------
// edge kernel: per CTA, 32 edges x 256 cols.
//   edge_input (577) -> silu(GEMM We1) -> silu(GEMM We2) = m_ij
//   m_ij -> silu(GEMM Wc1) -> dot Wc2 = coord_w
//   RED m_ij into g_mi[dst], RED rel_pos*coord_w into xout[dst]
// smem layout: sA[KIN][PITCH] (k-major input tile, reused for m1 / m_ij),
//              then rel(32*3), red(32*8), cw(32), idx(2*32 ints)
// ---------------------------------------------------------------------------
__global__ void __launch_bounds__(NTHREADS, 2)
edge_kernel(const float* __restrict__ h,  const float* __restrict__ x,
            const int*   __restrict__ ei, const float* __restrict__ ea,
            const float* __restrict__ We1, const float* __restrict__ be1,
            const float* __restrict__ We2, const float* __restrict__ be2,
            const float* __restrict__ Wc1, const float* __restrict__ bc1,
            const float* __restrict__ Wc2,
            float* __restrict__ mi, float* __restrict__ xout, int E)
{
    extern __shared__ float sm[];
    float* sA   = sm;                          // KIN * PITCH
    float* srel = sm + KIN * PITCH;            // TE*3
    float* sred = srel + TE * 3;               // TE*8
    float* scw  = sred + TE * 8;               // TE
    int*   sidx = (int*)(scw + TE);            // 2*TE

    const int tid   = threadIdx.x;
    const int e0    = blockIdx.x * TE;
    const int valid = min(TE, E - e0);

    // header: indices, rel_pos, dist_sq (row 512)
    if (tid < TE) {
        int s = 0, d = 0;
        float rx = 0.f, ry = 0.f, rz = 0.f, ds = 0.f;
        if (tid < valid) {
            int e = e0 + tid;
            s = ei[e]; d = ei[E + e];
            float ax = x[3*s], ay = x[3*s+1], az = x[3*s+2];
            float bx = x[3*d], by = x[3*d+1], bz = x[3*d+2];
            rx = ax - bx; ry = ay - by; rz = az - bz;
            ds = rx*rx + ry*ry + rz*rz;
        }
        sidx[tid]       = s;
        sidx[TE + tid]  = d;
        srel[3*tid]     = rx;
        srel[3*tid + 1] = ry;
        srel[3*tid + 2] = rz;
        sA[512 * PITCH + tid] = ds;
    }
    __syncthreads();

    // gather h[src] -> rows 0..255, h[dst] -> rows 256..511 (coalesced gmem,
    // conflict-free smem: word index c*33+e)
    #pragma unroll 1
    for (int i = 0; i < TE; i++) {
        int s = sidx[i], d = sidx[TE + i];
        sA[tid * PITCH + i]          = __ldg(&h[(size_t)s * HIDN + tid]);
        sA[(HIDN + tid) * PITCH + i] = __ldg(&h[(size_t)d * HIDN + tid]);
    }
    // edge_attr -> rows 513..576
    for (int i = tid; i < TE * EDIM; i += NTHREADS) {
        int e = i >> 6, c = i & 63;
        float v = 0.f;
        if (e < valid) v = __ldg(&ea[(size_t)(e0 + e) * EDIM + c]);
        sA[(513 + c) * PITCH + e] = v;
    }
    __syncthreads();

    const int j = tid;          // output column owned by this thread
    float acc[TE];

    // ---- GEMM1: (32 x 577) @ We1(577 x 256) ----
    {
        float b = be1[j];
        #pragma unroll
        for (int e = 0; e < TE; e++) acc[e] = b;
        #pragma unroll 2
        for (int k = 0; k < KIN; k++) {
            float w = __ldg(&We1[k * HIDN + j]);
            const float* r = sA + k * PITCH;
            #pragma unroll
            for (int e = 0; e < TE; e++) acc[e] = fmaf(r[e], w, acc[e]);
        }
    }
    __syncthreads();
    #pragma unroll
    for (int e = 0; e < TE; e++) sA[j * PITCH + e] = silu_f(acc[e]);   // m1 -> rows 0..255
    __syncthreads();

    // ---- GEMM2: m1 @ We2 -> m_ij ----
    {
        float b = be2[j];
        #pragma unroll
        for (int e = 0; e < TE; e++) acc[e] = b;
        #pragma unroll 2
        for (int k = 0; k < HIDN; k++) {
            float w = __ldg(&We2[k * HIDN + j]);
            const float* r = sA + k * PITCH;
            #pragma unroll
            for (int e = 0; e < TE; e++) acc[e] = fmaf(r[e], w, acc[e]);
        }
    }
    #pragma unroll
    for (int e = 0; e < TE; e++) acc[e] = silu_f(acc[e]);              // m_ij
    // stash m_ij in rows 256..511 (free after GEMM1; disjoint from GEMM2 reads)
    #pragma unroll
    for (int e = 0; e < TE; e++) sA[(HIDN + j) * PITCH + e] = acc[e];
    // scatter m_ij into g_mi[dst] straight from registers
    #pragma unroll
    for (int e = 0; e < TE; e++) {
        if (e < valid)
            atomicAdd(&mi[(size_t)sidx[TE + e] * HIDN + j], acc[e]);
    }
    __syncthreads();

    // ---- GEMM3: m_ij @ Wc1 -> silu -> dot Wc2 ----
    {
        float b = bc1[j];
        #pragma unroll
        for (int e = 0; e < TE; e++) acc[e] = b;
        #pragma unroll 2
        for (int k = 0; k < HIDN; k++) {
            float w = __ldg(&Wc1[k * HIDN + j]);
            const float* r = sA + (HIDN + k) * PITCH;
            #pragma unroll
            for (int e = 0; e < TE; e++) acc[e] = fmaf(r[e], w, acc[e]);
        }
    }
    const float wc2  = __ldg(&Wc2[j]);
    const int   lane = tid & 31, wrp = tid >> 5;
    #pragma unroll
    for (int e = 0; e < TE; e++) {
        float v = silu_f(acc[e]) * wc2;
        v += __shfl_down_sync(0xffffffffu, v, 16);
        v += __shfl_down_sync(0xffffffffu, v, 8);
        v += __shfl_down_sync(0xffffffffu, v, 4);
        v += __shfl_down_sync(0xffffffffu, v, 2);
        v += __shfl_down_sync(0xffffffffu, v, 1);
        if (lane == 0) sred[e * 8 + wrp] = v;
    }
    __syncthreads();
    if (tid < TE) {
        float cw = 0.f;
        #pragma unroll
        for (int w8 = 0; w8 < 8; w8++) cw += sred[tid * 8 + w8];
        scw[tid] = cw;
    }
    __syncthreads();
    if (tid < TE * 3) {
        int e = tid / 3, dd = tid - 3 * e;
        if (e < valid)
            atomicAdd(&xout[(size_t)sidx[TE + e] * 3 + dd],
                      srel[3 * e + dd] * scw[e]);
    }
}

// ---------------------------------------------------------------------------
// node kernel: h_out = h + silu([h, m_i] @ Wn1 + bn1) @ Wn2 + bn2
// per CTA: 32 nodes x 256 cols, same structure as edge kernel
// ---------------------------------------------------------------------------
__global__ void __launch_bounds__(NTHREADS, 2)
node_kernel(const float* __restrict__ h,   const float* __restrict__ mi,
            const float* __restrict__ Wn1, const float* __restrict__ bn1,
            const float* __restrict__ Wn2, const float* __restrict__ bn2,
            float* __restrict__ hout, int N)
{
    extern __shared__ float sm[];
    float* sA = sm;                           // 512 * PITCH
    const int tid   = threadIdx.x;
    const int n0    = blockIdx.x * TE;
    const int valid = min(TE, N - n0);

    #pragma unroll 1
    for (int i = 0; i < TE; i++) {
        float a = 0.f, b = 0.f;
        if (i < valid) {
            a = __ldg(&h [(size_t)(n0 + i) * HIDN + tid]);
            b = __ldg(&mi[(size_t)(n0 + i) * HIDN + tid]);
        }
        sA[tid * PITCH + i]          = a;     // rows 0..255 : h
        sA[(HIDN + tid) * PITCH + i] = b;     // rows 256..511: m_i
    }
    __syncthreads();

    const int j = tid;
    float acc[TE];
    {
        float b = bn1[j];
        #pragma unroll
        for (int e = 0; e < TE; e++) acc[e] = b;
        #pragma unroll 2
        for (int k = 0; k < 2 * HIDN; k++) {
            float w = __ldg(&Wn1[k * HIDN + j]);
            const float* r = sA + k * PITCH;
            #pragma unroll
            for (int e = 0; e < TE; e++) acc[e] = fmaf(r[e], w, acc[e]);
        }
    }
    __syncthreads();
    #pragma unroll
    for (int e = 0; e < TE; e++) sA[j * PITCH + e] = silu_f(acc[e]);
    __syncthreads();
    {
        float b = bn2[j];
        #pragma unroll
        for (int e = 0; e < TE; e++) acc[e] = b;
        #pragma unroll 2
        for (int k = 0; k < HIDN; k++) {
            float w = __ldg(&Wn2[k * HIDN + j]);
            const float* r = sA + k * PITCH;
            #pragma unroll
            for (int e = 0; e < TE; e++) acc[e] = fmaf(r[e], w, acc[e]);
        }
    }
    #pragma unroll
    for (int e = 0; e < TE; e++) {
        if (e < valid)
            hout[(size_t)(n0 + e) * HIDN + j] =
                __ldg(&h[(size_t)(n0 + e) * HIDN + j]) + acc[e];
    }
}

// ---------------------------------------------------------------------------
extern "C" void kernel_launch(void* const* d_in, const int* in_sizes, int n_in,
                              void* d_out, int out_size)
{
    const float* h   = (const float*)d_in[0];
    const float* x   = (const float*)d_in[1];
    const int*   ei  = (const int*)  d_in[2];
    const float* ea  = (const float*)d_in[3];
    const float* We1 = (const float*)d_in[4];
    const float* be1 = (const float*)d_in[5];
    const float* We2 = (const float*)d_in[6];
    const float* be2 = (const float*)d_in[7];
    const float* Wn1 = (const float*)d_in[8];
    const float* bn1 = (const float*)d_in[9];
    const float* Wn2 = (const float*)d_in[10];
    const float* bn2 = (const float*)d_in[11];
    const float* Wc1 = (const float*)d_in[12];
    const float* bc1 = (const float*)d_in[13];
    const float* Wc2 = (const float*)d_in[14];

    const int N = in_sizes[0] / HIDN;
    const int E = in_sizes[2] / 2;

    float* hout = (float*)d_out;                 // (N, 256) first output
    float* xout = hout + (size_t)N * HIDN;       // (N, 3)   second output

    float* mi = nullptr;
    cudaGetSymbolAddress((void**)&mi, g_mi);

    const int ESM = (KIN * PITCH + TE * 3 + TE * 8 + TE) * (int)sizeof(float)
                    + 2 * TE * (int)sizeof(int);
    const int NSM = (2 * HIDN * PITCH) * (int)sizeof(float);
    cudaFuncSetAttribute(edge_kernel, cudaFuncAttributeMaxDynamicSharedMemorySize, ESM);
    cudaFuncSetAttribute(node_kernel, cudaFuncAttributeMaxDynamicSharedMemorySize, NSM);

    const int totmi = N * HIDN;
    init_kernel<<<(totmi + NTHREADS - 1) / NTHREADS, NTHREADS>>>(x, mi, xout, totmi, N * 3);
    edge_kernel<<<(E + TE - 1) / TE, NTHREADS, ESM>>>(h, x, ei, ea,
                                                      We1, be1, We2, be2,
                                                      Wc1, bc1, Wc2,
                                                      mi, xout, E);
    node_kernel<<<(N + TE - 1) / TE, NTHREADS, NSM>>>(h, mi, Wn1, bn1, Wn2, bn2, hout, N);
}

// round 2
// speedup vs baseline: 1.1783x; 1.1783x over previous
#include <cuda_runtime.h>

#define HIDN 256
#define EDIM 64
#define KIN  577        // 2*HID + 1 + EDGE_DIM
#define TE   32         // edges (or nodes) per CTA
#define NTHREADS 256
#define PITCH 34        // smem row pitch: 8B-aligned rows -> LDS.64, 2-way store conflict
#define MAXN 50000

typedef unsigned long long u64;

// scratch: per-node aggregated messages m_i  (50000 * 256 floats = 51.2 MB)
__device__ float g_mi[(size_t)MAXN * HIDN];

__device__ __forceinline__ float silu_f(float v) {
    return v * (1.0f / (1.0f + __expf(-v)));
}

// ---- packed fp32x2 helpers -------------------------------------------------
__device__ __forceinline__ u64 splat2(float w) {
    u64 r;
    asm("mov.b64 %0, {%1, %1};" : "=l"(r) : "r"(__float_as_uint(w)));
    return r;
}
__device__ __forceinline__ u64 pack2(float a, float b) {
    u64 r;
    asm("mov.b64 %0, {%1, %2};" : "=l"(r) : "r"(__float_as_uint(a)), "r"(__float_as_uint(b)));
    return r;
}
__device__ __forceinline__ float2 unpack2(u64 v) {
    unsigned lo, hi;
    asm("mov.b64 {%0, %1}, %2;" : "=r"(lo), "=r"(hi) : "l"(v));
    return make_float2(__uint_as_float(lo), __uint_as_float(hi));
}
__device__ __forceinline__ void fma2(u64& a, u64 b, u64 c) {
    asm("fma.rn.f32x2 %0, %1, %2, %0;" : "+l"(a) : "l"(b), "l"(c));
}

// GEMM core: 16 packed accumulators (32 edges/nodes), thread owns column j.
// base = sA + row0*PITCH (k-major tile, 8B-aligned rows), W row-major (K x 256).
template<int K>
__device__ __forceinline__ void gemm_core(u64 acc[16],
                                          const float* __restrict__ base,
                                          const float* __restrict__ W,
                                          int j, float bias)
{
    u64 b2 = splat2(bias);
    #pragma unroll
    for (int p = 0; p < 16; p++) acc[p] = b2;
    #pragma unroll 4
    for (int k = 0; k < K; k++) {
        u64 w2 = splat2(__ldg(&W[k * HIDN + j]));
        const u64* r2 = (const u64*)(base + (size_t)k * PITCH);
        #pragma unroll
        for (int p = 0; p < 16; p++) fma2(acc[p], r2[p], w2);
    }
}

// ---------------------------------------------------------------------------
__global__ void init_kernel(const float* __restrict__ x,
                            float* __restrict__ mi,
                            float* __restrict__ xout,
                            int total_mi, int total_x)
{
    int i = blockIdx.x * blockDim.x + threadIdx.x;
    if (i < total_mi) mi[i] = 0.0f;
    if (i < total_x)  xout[i] = x[i];
}

// ---------------------------------------------------------------------------
// edge kernel: per CTA, 32 edges x 256 cols.
// ---------------------------------------------------------------------------
__global__ void __launch_bounds__(NTHREADS, 2)
edge_kernel(const float* __restrict__ h,  const float* __restrict__ x,
            const int*   __restrict__ ei, const float* __restrict__ ea,
            const float* __restrict__ We1, const float* __restrict__ be1,
            const float* __restrict__ We2, const float* __restrict__ be2,
            const float* __restrict__ Wc1, const float* __restrict__ bc1,
            const float* __restrict__ Wc2,
            float* __restrict__ mi, float* __restrict__ xout, int E)
{
    extern __shared__ float sm[];
    float* sA   = sm;                          // KIN * PITCH
    float* srel = sm + KIN * PITCH;            // TE*3
    float* sred = srel + TE * 3;               // TE*8
    float* scw  = sred + TE * 8;               // TE
    int*   sidx = (int*)(scw + TE);            // 2*TE

    const int tid   = threadIdx.x;
    const int e0    = blockIdx.x * TE;
    const int valid = min(TE, E - e0);

    // header: indices, rel_pos, dist_sq (row 512)
    if (tid < TE) {
        int s = 0, d = 0;
        float rx = 0.f, ry = 0.f, rz = 0.f, ds = 0.f;
        if (tid < valid) {
            int e = e0 + tid;
            s = ei[e]; d = ei[E + e];
            float ax = x[3*s], ay = x[3*s+1], az = x[3*s+2];
            float bx = x[3*d], by = x[3*d+1], bz = x[3*d+2];
            rx = ax - bx; ry = ay - by; rz = az - bz;
            ds = rx*rx + ry*ry + rz*rz;
        }
        sidx[tid]       = s;
        sidx[TE + tid]  = d;
        srel[3*tid]     = rx;
        srel[3*tid + 1] = ry;
        srel[3*tid + 2] = rz;
        sA[2 * HIDN * PITCH + tid] = ds;
    }
    __syncthreads();

    // gather h[src] -> rows 0..255, h[dst] -> rows 256..511
    #pragma unroll 1
    for (int i = 0; i < TE; i++) {
        int s = sidx[i], d = sidx[TE + i];
        sA[tid * PITCH + i]          = __ldg(&h[(size_t)s * HIDN + tid]);
        sA[(HIDN + tid) * PITCH + i] = __ldg(&h[(size_t)d * HIDN + tid]);
    }
    // edge_attr -> rows 513..576
    for (int i = tid; i < TE * EDIM; i += NTHREADS) {
        int e = i >> 6, c = i & 63;
        float v = 0.f;
        if (e < valid) v = __ldg(&ea[(size_t)(e0 + e) * EDIM + c]);
        sA[(2 * HIDN + 1 + c) * PITCH + e] = v;
    }
    __syncthreads();

    const int j = tid;
    u64 acc[16];

    // ---- GEMM1: (32 x 577) @ We1 ----
    gemm_core<KIN>(acc, sA, We1, j, be1[j]);
    __syncthreads();
    {
        u64* row = (u64*)(sA + (size_t)j * PITCH);   // m1 -> rows 0..255
        #pragma unroll
        for (int p = 0; p < 16; p++) {
            float2 v = unpack2(acc[p]);
            row[p] = pack2(silu_f(v.x), silu_f(v.y));
        }
    }
    __syncthreads();

    // ---- GEMM2: m1 @ We2 -> m_ij ----
    gemm_core<HIDN>(acc, sA, We2, j, be2[j]);
    float m[TE];
    #pragma unroll
    for (int p = 0; p < 16; p++) {
        float2 v = unpack2(acc[p]);
        m[2*p]   = silu_f(v.x);
        m[2*p+1] = silu_f(v.y);
    }
    {
        u64* row = (u64*)(sA + (size_t)(HIDN + j) * PITCH);  // m_ij -> rows 256..511
        #pragma unroll
        for (int p = 0; p < 16; p++) row[p] = pack2(m[2*p], m[2*p+1]);
    }
    // scatter m_ij into g_mi[dst]
    #pragma unroll
    for (int e = 0; e < TE; e++) {
        if (e < valid)
            atomicAdd(&mi[(size_t)sidx[TE + e] * HIDN + j], m[e]);
    }
    __syncthreads();

    // ---- GEMM3: m_ij @ Wc1 -> silu -> dot Wc2 ----
    gemm_core<HIDN>(acc, sA + (size_t)HIDN * PITCH, Wc1, j, bc1[j]);

    const float wc2  = __ldg(&Wc2[j]);
    const int   lane = tid & 31, wrp = tid >> 5;
    #pragma unroll
    for (int p = 0; p < 16; p++) {
        float2 vv = unpack2(acc[p]);
        #pragma unroll
        for (int q = 0; q < 2; q++) {
            float v = silu_f(q ? vv.y : vv.x) * wc2;
            v += __shfl_down_sync(0xffffffffu, v, 16);
            v += __shfl_down_sync(0xffffffffu, v, 8);
            v += __shfl_down_sync(0xffffffffu, v, 4);
            v += __shfl_down_sync(0xffffffffu, v, 2);
            v += __shfl_down_sync(0xffffffffu, v, 1);
            if (lane == 0) sred[(2*p + q) * 8 + wrp] = v;
        }
    }
    __syncthreads();
    if (tid < TE) {
        float cw = 0.f;
        #pragma unroll
        for (int w8 = 0; w8 < 8; w8++) cw += sred[tid * 8 + w8];
        scw[tid] = cw;
    }
    __syncthreads();
    if (tid < TE * 3) {
        int e = tid / 3, dd = tid - 3 * e;
        if (e < valid)
            atomicAdd(&xout[(size_t)sidx[TE + e] * 3 + dd],
                      srel[3 * e + dd] * scw[e]);
    }
}

// ---------------------------------------------------------------------------
// node kernel: h_out = h + silu([h, m_i] @ Wn1 + bn1) @ Wn2 + bn2
// ---------------------------------------------------------------------------
__global__ void __launch_bounds__(NTHREADS, 2)
node_kernel(const float* __restrict__ h,   const float* __restrict__ mi,
            const float* __restrict__ Wn1, const float* __restrict__ bn1,
            const float* __restrict__ Wn2, const float* __restrict__ bn2,
            float* __restrict__ hout, int N)
{
    extern __shared__ float sm[];
    float* sA = sm;                           // 512 * PITCH
    const int tid   = threadIdx.x;
    const int n0    = blockIdx.x * TE;
    const int valid = min(TE, N - n0);

    #pragma unroll 1
    for (int i = 0; i < TE; i++) {
        float a = 0.f, b = 0.f;
        if (i < valid) {
            a = __ldg(&h [(size_t)(n0 + i) * HIDN + tid]);
            b = __ldg(&mi[(size_t)(n0 + i) * HIDN + tid]);
        }
        sA[tid * PITCH + i]          = a;     // rows 0..255 : h
        sA[(HIDN + tid) * PITCH + i] = b;     // rows 256..511: m_i
    }
    __syncthreads();

    const int j = tid;
    u64 acc[16];

    gemm_core<2 * HIDN>(acc, sA, Wn1, j, bn1[j]);
    __syncthreads();
    {
        u64* row = (u64*)(sA + (size_t)j * PITCH);
        #pragma unroll
        for (int p = 0; p < 16; p++) {
            float2 v = unpack2(acc[p]);
            row[p] = pack2(silu_f(v.x), silu_f(v.y));
        }
    }
    __syncthreads();

    gemm_core<HIDN>(acc, sA, Wn2, j, bn2[j]);

    #pragma unroll
    for (int p = 0; p < 16; p++) {
        float2 v = unpack2(acc[p]);
        int e = 2 * p;
        if (e < valid)
            hout[(size_t)(n0 + e) * HIDN + j] =
                __ldg(&h[(size_t)(n0 + e) * HIDN + j]) + v.x;
        if (e + 1 < valid)
            hout[(size_t)(n0 + e + 1) * HIDN + j] =
                __ldg(&h[(size_t)(n0 + e + 1) * HIDN + j]) + v.y;
    }
}

// ---------------------------------------------------------------------------
extern "C" void kernel_launch(void* const* d_in, const int* in_sizes, int n_in,
                              void* d_out, int out_size)
{
    const float* h   = (const float*)d_in[0];
    const float* x   = (const float*)d_in[1];
    const int*   ei  = (const int*)  d_in[2];
    const float* ea  = (const float*)d_in[3];
    const float* We1 = (const float*)d_in[4];
    const float* be1 = (const float*)d_in[5];
    const float* We2 = (const float*)d_in[6];
    const float* be2 = (const float*)d_in[7];
    const float* Wn1 = (const float*)d_in[8];
    const float* bn1 = (const float*)d_in[9];
    const float* Wn2 = (const float*)d_in[10];
    const float* bn2 = (const float*)d_in[11];
    const float* Wc1 = (const float*)d_in[12];
    const float* bc1 = (const float*)d_in[13];
    const float* Wc2 = (const float*)d_in[14];

    const int N = in_sizes[0] / HIDN;
    const int E = in_sizes[2] / 2;

    float* hout = (float*)d_out;                 // (N, 256) first output
    float* xout = hout + (size_t)N * HIDN;       // (N, 3)   second output

    float* mi = nullptr;
    cudaGetSymbolAddress((void**)&mi, g_mi);

    const int ESM = (KIN * PITCH + TE * 3 + TE * 8 + TE) * (int)sizeof(float)
                    + 2 * TE * (int)sizeof(int);
    const int NSM = (2 * HIDN * PITCH) * (int)sizeof(float);
    cudaFuncSetAttribute(edge_kernel, cudaFuncAttributeMaxDynamicSharedMemorySize, ESM);
    cudaFuncSetAttribute(node_kernel, cudaFuncAttributeMaxDynamicSharedMemorySize, NSM);

    const int totmi = N * HIDN;
    init_kernel<<<(totmi + NTHREADS - 1) / NTHREADS, NTHREADS>>>(x, mi, xout, totmi, N * 3);
    edge_kernel<<<(E + TE - 1) / TE, NTHREADS, ESM>>>(h, x, ei, ea,
                                                      We1, be1, We2, be2,
                                                      Wc1, bc1, Wc2,
                                                      mi, xout, E);
    node_kernel<<<(N + TE - 1) / TE, NTHREADS, NSM>>>(h, mi, Wn1, bn1, Wn2, bn2, hout, N);
}

// round 3
// speedup vs baseline: 2.3993x; 2.0362x over previous
#include <cuda_runtime.h>
#include <cuda_bf16.h>

typedef unsigned int u32;
typedef unsigned long long u64;

#define HIDN 256
#define EDIM 64
#define KIN  577
#define MAXN 50000

// edge kernel tiling
#define EM   128          // edges per CTA
#define ETH  512          // threads per CTA (16 warps, 4x4)
#define NC1  37           // ceil(592/16) chunks for GEMM1 (K padded 577->592)
#define NC2  16           // 256/16 chunks for GEMM2/3

// node kernel (unchanged from R2)
#define TE   32
#define NTHREADS 256
#define PITCH 34

// smem word offsets (fp32 words)
#define OFF_BIAS  0        // 1024: be1,be2,bc1,wc2
#define OFF_IDXS  1024     // 128 ints
#define OFF_IDXD  1152     // 128 ints
#define OFF_REL   1280     // 384
#define OFF_DIST  1664     // 128
#define OFF_COORD 1792     // 128
#define OFF_M     1920     // 128*258 = 33024 (m1 / m_ij fp32, pitch 258)
#define OFF_A     34944    // u32: 2 buf * 2 planes * 1152 (pitch 9)
#define OFF_B     39552    // u32: 2 buf * 2 planes * 2304 (pitch 9)
#define SMEM_WORDS 48768   // 195072 bytes

__device__ float g_mi[(size_t)MAXN * HIDN];

__device__ __forceinline__ float silu_f(float v) {
    return v * (1.0f / (1.0f + __expf(-v)));
}

// ---- fp32 -> (hi,lo) bf16 split --------------------------------------------
__device__ __forceinline__ void bsplit(float v, u32& hi, u32& lo) {
    __nv_bfloat16 h = __float2bfloat16(v);
    float r = v - __bfloat162float(h);
    __nv_bfloat16 l = __float2bfloat16(r);
    hi = (u32)__bfloat16_as_ushort(h);
    lo = (u32)__bfloat16_as_ushort(l);
}

__device__ __forceinline__ void mma_bf16(float c[4], const u32 a[4], u32 b0, u32 b1) {
    asm volatile(
        "mma.sync.aligned.m16n8k16.row.col.f32.bf16.bf16.f32 "
        "{%0,%1,%2,%3}, {%4,%5,%6,%7}, {%8,%9}, {%0,%1,%2,%3};"
        : "+f"(c[0]), "+f"(c[1]), "+f"(c[2]), "+f"(c[3])
        : "r"(a[0]), "r"(a[1]), "r"(a[2]), "r"(a[3]), "r"(b0), "r"(b1));
}

// ---- chunk loaders (regs) and stores (smem) --------------------------------
// A tile: 128 rows x 16 k per chunk. item = tid + i*ETH; row = item>>3, kp = item&7
template<int MODE>   // 0: edge composite input, 1: from sM (fp32, pitch 258)
__device__ __forceinline__ void load_A_regs(float av[4], int c,
    const float* __restrict__ h, const float* __restrict__ ea,
    const int* sS, const int* sD, const float* sdist, const float* sM,
    int tid, int e0, int valid)
{
    int k0 = c * 16;
    #pragma unroll
    for (int i = 0; i < 2; i++) {
        int item = tid + i * ETH;
        int row = item >> 3, kp = item & 7;
        int k = k0 + 2 * kp;
        float v0, v1;
        if (MODE == 0) {
            if (k + 1 < 256) {
                const float* p = h + (size_t)sS[row] * HIDN + k;
                v0 = __ldg(p); v1 = __ldg(p + 1);
            } else if (k + 1 < 512) {
                const float* p = h + (size_t)sD[row] * HIDN + (k - 256);
                v0 = __ldg(p); v1 = __ldg(p + 1);
            } else {
                v0 = (k == 512) ? sdist[row]
                   : ((k >= 513 && k <= 576 && row < valid)
                        ? __ldg(&ea[(size_t)(e0 + row) * EDIM + (k - 513)]) : 0.f);
                int k1 = k + 1;
                v1 = (k1 == 512) ? sdist[row]
                   : ((k1 >= 513 && k1 <= 576 && row < valid)
                        ? __ldg(&ea[(size_t)(e0 + row) * EDIM + (k1 - 513)]) : 0.f);
            }
        } else {
            const float2 p = *(const float2*)(sM + row * 258 + k);
            v0 = p.x; v1 = p.y;
        }
        av[2 * i] = v0; av[2 * i + 1] = v1;
    }
}

__device__ __forceinline__ void store_A(const float av[4], u32* sAh, u32* sAl, int tid)
{
    #pragma unroll
    for (int i = 0; i < 2; i++) {
        int item = tid + i * ETH;
        int row = item >> 3, kp = item & 7;
        u32 h0, l0, h1, l1;
        bsplit(av[2 * i], h0, l0);
        bsplit(av[2 * i + 1], h1, l1);
        sAh[row * 9 + kp] = h0 | (h1 << 16);
        sAl[row * 9 + kp] = l0 | (l1 << 16);
    }
}

// B tile: 16 k x 256 n per chunk. item = tid + i*ETH; kp = item>>8, n = item&255
__device__ __forceinline__ void load_B_regs(float bv[8], int c,
    const float* __restrict__ W, int Kmax, int tid)
{
    int k0 = c * 16;
    #pragma unroll
    for (int i = 0; i < 4; i++) {
        int item = tid + i * ETH;
        int kp = item >> 8, n = item & 255;
        int k = k0 + 2 * kp;
        bv[2 * i]     = (k     < Kmax) ? __ldg(&W[(size_t)k * HIDN + n])       : 0.f;
        bv[2 * i + 1] = (k + 1 < Kmax) ? __ldg(&W[(size_t)(k + 1) * HIDN + n]) : 0.f;
    }
}

__device__ __forceinline__ void store_B(const float bv[8], u32* sBh, u32* sBl, int tid)
{
    #pragma unroll
    for (int i = 0; i < 4; i++) {
        int item = tid + i * ETH;
        int kp = item >> 8, n = item & 255;
        u32 h0, l0, h1, l1;
        bsplit(bv[2 * i], h0, l0);
        bsplit(bv[2 * i + 1], h1, l1);
        sBh[n * 9 + kp] = h0 | (h1 << 16);
        sBl[n * 9 + kp] = l0 | (l1 << 16);
    }
}

// ---- one k=16 chunk of 3-pass split MMA over the warp's 32x64 tile ---------
__device__ __forceinline__ void mma_chunk(const u32* __restrict__ Ah, const u32* __restrict__ Al,
                                          const u32* __restrict__ Bh, const u32* __restrict__ Bl,
                                          float (*acc)[4], int wm, int wn, int g, int tig)
{
    u32 ah[2][4], al[2][4];
    #pragma unroll
    for (int mt = 0; mt < 2; mt++) {
        int r = wm * 32 + mt * 16 + g;
        ah[mt][0] = Ah[r * 9 + tig];       ah[mt][1] = Ah[(r + 8) * 9 + tig];
        ah[mt][2] = Ah[r * 9 + tig + 4];   ah[mt][3] = Ah[(r + 8) * 9 + tig + 4];
        al[mt][0] = Al[r * 9 + tig];       al[mt][1] = Al[(r + 8) * 9 + tig];
        al[mt][2] = Al[r * 9 + tig + 4];   al[mt][3] = Al[(r + 8) * 9 + tig + 4];
    }
    #pragma unroll
    for (int nt = 0; nt < 8; nt++) {
        int n = wn * 64 + nt * 8 + g;
        u32 bh0 = Bh[n * 9 + tig], bh1 = Bh[n * 9 + tig + 4];
        u32 bl0 = Bl[n * 9 + tig], bl1 = Bl[n * 9 + tig + 4];
        #pragma unroll
        for (int mt = 0; mt < 2; mt++) {
            mma_bf16(acc[mt * 8 + nt], ah[mt], bh0, bh1);
            mma_bf16(acc[mt * 8 + nt], ah[mt], bl0, bl1);
            mma_bf16(acc[mt * 8 + nt], al[mt], bh0, bh1);
        }
    }
}

// ---- full GEMM: acc(128x256) += A(128xK) @ W(KxHIDN), double-buffered ------
template<int MODE, int NCV>
__device__ __forceinline__ void run_gemm(float (*acc)[4],
    const float* __restrict__ W, int Kmax,
    const float* __restrict__ h, const float* __restrict__ ea,
    const int* sS, const int* sD, const float* sdist, const float* sM,
    u32* sA, u32* sB, int tid, int e0, int valid,
    int wm, int wn, int g, int tig)
{
    #pragma unroll
    for (int q = 0; q < 16; q++) { acc[q][0] = 0.f; acc[q][1] = 0.f; acc[q][2] = 0.f; acc[q][3] = 0.f; }

    float av[4], bv[8];
    load_A_regs<MODE>(av, 0, h, ea, sS, sD, sdist, sM, tid, e0, valid);
    load_B_regs(bv, 0, W, Kmax, tid);
    store_A(av, sA, sA + 1152, tid);
    store_B(bv, sB, sB + 2304, tid);
    __syncthreads();

    for (int c = 0; c < NCV; c++) {
        int cb = c & 1, nb = (c + 1) & 1;
        if (c + 1 < NCV) {
            load_A_regs<MODE>(av, c + 1, h, ea, sS, sD, sdist, sM, tid, e0, valid);
            load_B_regs(bv, c + 1, W, Kmax, tid);
        }
        mma_chunk(sA + cb * 2304, sA + cb * 2304 + 1152,
                  sB + cb * 4608, sB + cb * 4608 + 2304,
                  acc, wm, wn, g, tig);
        if (c + 1 < NCV) {
            store_A(av, sA + nb * 2304, sA + nb * 2304 + 1152, tid);
            store_B(bv, sB + nb * 4608, sB + nb * 4608 + 2304, tid);
        }
        __syncthreads();
    }
}

// ---------------------------------------------------------------------------
__global__ void init_kernel(const float* __restrict__ x,
                            float* __restrict__ mi,
                            float* __restrict__ xout,
                            int total_mi, int total_x)
{
    int i = blockIdx.x * blockDim.x + threadIdx.x;
    if (i < total_mi) mi[i] = 0.0f;
    if (i < total_x)  xout[i] = x[i];
}

// ---------------------------------------------------------------------------
__global__ void __launch_bounds__(ETH, 1)
edge_kernel_mma(const float* __restrict__ h,  const float* __restrict__ x,
                const int*   __restrict__ ei, const float* __restrict__ ea,
                const float* __restrict__ We1, const float* __restrict__ be1,
                const float* __restrict__ We2, const float* __restrict__ be2,
                const float* __restrict__ Wc1, const float* __restrict__ bc1,
                const float* __restrict__ Wc2,
                float* __restrict__ mi, float* __restrict__ xout, int E)
{
    extern __shared__ float sm[];
    float* sBias  = sm + OFF_BIAS;
    int*   sS     = (int*)(sm + OFF_IDXS);
    int*   sD     = (int*)(sm + OFF_IDXD);
    float* srel   = sm + OFF_REL;
    float* sdist  = sm + OFF_DIST;
    float* scoord = sm + OFF_COORD;
    float* sM     = sm + OFF_M;
    u32*   sA     = (u32*)(sm + OFF_A);
    u32*   sB     = (u32*)(sm + OFF_B);

    const int tid  = threadIdx.x;
    const int wid  = tid >> 5, lane = tid & 31;
    const int wm   = wid >> 2, wn = wid & 3;       // 4x4 warp grid
    const int g    = lane >> 2, tig = lane & 3;
    const int e0   = blockIdx.x * EM;
    const int valid = min(EM, E - e0);

    // stage biases + wc2
    if (tid < 256) {
        sBias[tid]       = be1[tid];
        sBias[256 + tid] = be2[tid];
        sBias[512 + tid] = bc1[tid];
        sBias[768 + tid] = __ldg(&Wc2[tid]);
    }
    // per-edge header
    if (tid < EM) {
        int s = 0, d = 0;
        float rx = 0.f, ry = 0.f, rz = 0.f, ds = 0.f;
        if (tid < valid) {
            int e = e0 + tid;
            s = ei[e]; d = ei[E + e];
            float ax = x[3*s], ay = x[3*s+1], az = x[3*s+2];
            float bx = x[3*d], by = x[3*d+1], bz = x[3*d+2];
            rx = ax - bx; ry = ay - by; rz = az - bz;
            ds = rx*rx + ry*ry + rz*rz;
        }
        sS[tid] = s; sD[tid] = d;
        srel[3*tid] = rx; srel[3*tid+1] = ry; srel[3*tid+2] = rz;
        sdist[tid] = ds;
    }
    __syncthreads();

    float acc[16][4];

    // ==== GEMM1: edge_input(128x577) @ We1 -> silu -> sM =====================
    run_gemm<0, NC1>(acc, We1, KIN, h, ea, sS, sD, sdist, sM,
                     sA, sB, tid, e0, valid, wm, wn, g, tig);
    #pragma unroll
    for (int mt = 0; mt < 2; mt++)
    #pragma unroll
    for (int nt = 0; nt < 8; nt++) {
        float* c = acc[mt * 8 + nt];
        int r0 = wm * 32 + mt * 16 + g;
        int c0 = wn * 64 + nt * 8 + 2 * tig;
        float b0 = sBias[c0], b1 = sBias[c0 + 1];
        *(float2*)(sM + r0 * 258 + c0)       = make_float2(silu_f(c[0] + b0), silu_f(c[1] + b1));
        *(float2*)(sM + (r0 + 8) * 258 + c0) = make_float2(silu_f(c[2] + b0), silu_f(c[3] + b1));
    }
    __syncthreads();

    // ==== GEMM2: m1 @ We2 -> silu = m_ij; scatter to mi; m_ij -> sM ==========
    run_gemm<1, NC2>(acc, We2, HIDN, h, ea, sS, sD, sdist, sM,
                     sA, sB, tid, e0, valid, wm, wn, g, tig);
    #pragma unroll
    for (int mt = 0; mt < 2; mt++)
    #pragma unroll
    for (int nt = 0; nt < 8; nt++) {
        float* c = acc[mt * 8 + nt];
        int r0 = wm * 32 + mt * 16 + g;
        int c0 = wn * 64 + nt * 8 + 2 * tig;
        float b0 = sBias[256 + c0], b1 = sBias[256 + c0 + 1];
        float m00 = silu_f(c[0] + b0), m01 = silu_f(c[1] + b1);
        float m10 = silu_f(c[2] + b0), m11 = silu_f(c[3] + b1);
        *(float2*)(sM + r0 * 258 + c0)       = make_float2(m00, m01);
        *(float2*)(sM + (r0 + 8) * 258 + c0) = make_float2(m10, m11);
        if (r0 < valid) {
            float* p = mi + (size_t)sD[r0] * HIDN + c0;
            atomicAdd(p, m00); atomicAdd(p + 1, m01);
        }
        if (r0 + 8 < valid) {
            float* p = mi + (size_t)sD[r0 + 8] * HIDN + c0;
            atomicAdd(p, m10); atomicAdd(p + 1, m11);
        }
    }
    if (tid < EM) scoord[tid] = 0.f;
    __syncthreads();

    // ==== GEMM3: m_ij @ Wc1 -> silu -> dot wc2 -> coord scatter ==============
    run_gemm<1, NC2>(acc, Wc1, HIDN, h, ea, sS, sD, sdist, sM,
                     sA, sB, tid, e0, valid, wm, wn, g, tig);
    {
        float rs[2][2] = {{0.f, 0.f}, {0.f, 0.f}};
        #pragma unroll
        for (int mt = 0; mt < 2; mt++)
        #pragma unroll
        for (int nt = 0; nt < 8; nt++) {
            float* c = acc[mt * 8 + nt];
            int c0 = wn * 64 + nt * 8 + 2 * tig;
            float b0 = sBias[512 + c0], b1 = sBias[512 + c0 + 1];
            float w0 = sBias[768 + c0], w1 = sBias[768 + c0 + 1];
            rs[mt][0] += silu_f(c[0] + b0) * w0 + silu_f(c[1] + b1) * w1;
            rs[mt][1] += silu_f(c[2] + b0) * w0 + silu_f(c[3] + b1) * w1;
        }
        #pragma unroll
        for (int mt = 0; mt < 2; mt++)
        #pragma unroll
        for (int hh = 0; hh < 2; hh++) {
            float v = rs[mt][hh];
            v += __shfl_xor_sync(0xffffffffu, v, 1);
            v += __shfl_xor_sync(0xffffffffu, v, 2);
            rs[mt][hh] = v;
        }
        if (tig == 0) {
            int r0 = wm * 32 + g;
            atomicAdd(&scoord[r0 + 0],  rs[0][0]);
            atomicAdd(&scoord[r0 + 8],  rs[0][1]);
            atomicAdd(&scoord[r0 + 16], rs[1][0]);
            atomicAdd(&scoord[r0 + 24], rs[1][1]);
        }
    }
    __syncthreads();
    if (tid < EM * 3) {
        int e = tid / 3, d = tid - 3 * e;
        if (e < valid)
            atomicAdd(&xout[(size_t)sD[e] * 3 + d], srel[3 * e + d] * scoord[e]);
    }
}

// ---------------------------------------------------------------------------
// node kernel (fp32x2, unchanged from R2)
// ---------------------------------------------------------------------------
__device__ __forceinline__ u64 splat2(float w) {
    u64 r; asm("mov.b64 %0, {%1, %1};" : "=l"(r) : "r"(__float_as_uint(w))); return r;
}
__device__ __forceinline__ u64 pack2(float a, float b) {
    u64 r; asm("mov.b64 %0, {%1, %2};" : "=l"(r) : "r"(__float_as_uint(a)), "r"(__float_as_uint(b))); return r;
}
__device__ __forceinline__ float2 unpack2(u64 v) {
    unsigned lo, hi; asm("mov.b64 {%0, %1}, %2;" : "=r"(lo), "=r"(hi) : "l"(v));
    return make_float2(__uint_as_float(lo), __uint_as_float(hi));
}
__device__ __forceinline__ void fma2(u64& a, u64 b, u64 c) {
    asm("fma.rn.f32x2 %0, %1, %2, %0;" : "+l"(a) : "l"(b), "l"(c));
}

template<int K>
__device__ __forceinline__ void gemm_core(u64 acc[16],
                                          const float* __restrict__ base,
                                          const float* __restrict__ W,
                                          int j, float bias)
{
    u64 b2 = splat2(bias);
    #pragma unroll
    for (int p = 0; p < 16; p++) acc[p] = b2;
    #pragma unroll 4
    for (int k = 0; k < K; k++) {
        u64 w2 = splat2(__ldg(&W[k * HIDN + j]));
        const u64* r2 = (const u64*)(base + (size_t)k * PITCH);
        #pragma unroll
        for (int p = 0; p < 16; p++) fma2(acc[p], r2[p], w2);
    }
}

__global__ void __launch_bounds__(NTHREADS, 2)
node_kernel(const float* __restrict__ h,   const float* __restrict__ mi,
            const float* __restrict__ Wn1, const float* __restrict__ bn1,
            const float* __restrict__ Wn2, const float* __restrict__ bn2,
            float* __restrict__ hout, int N)
{
    extern __shared__ float smn[];
    float* sA = smn;
    const int tid   = threadIdx.x;
    const int n0    = blockIdx.x * TE;
    const int valid = min(TE, N - n0);

    #pragma unroll 1
    for (int i = 0; i < TE; i++) {
        float a = 0.f, b = 0.f;
        if (i < valid) {
            a = __ldg(&h [(size_t)(n0 + i) * HIDN + tid]);
            b = __ldg(&mi[(size_t)(n0 + i) * HIDN + tid]);
        }
        sA[tid * PITCH + i]          = a;
        sA[(HIDN + tid) * PITCH + i] = b;
    }
    __syncthreads();

    const int j = tid;
    u64 acc[16];

    gemm_core<2 * HIDN>(acc, sA, Wn1, j, bn1[j]);
    __syncthreads();
    {
        u64* row = (u64*)(sA + (size_t)j * PITCH);
        #pragma unroll
        for (int p = 0; p < 16; p++) {
            float2 v = unpack2(acc[p]);
            row[p] = pack2(silu_f(v.x), silu_f(v.y));
        }
    }
    __syncthreads();

    gemm_core<HIDN>(acc, sA, Wn2, j, bn2[j]);

    #pragma unroll
    for (int p = 0; p < 16; p++) {
        float2 v = unpack2(acc[p]);
        int e = 2 * p;
        if (e < valid)
            hout[(size_t)(n0 + e) * HIDN + j] =
                __ldg(&h[(size_t)(n0 + e) * HIDN + j]) + v.x;
        if (e + 1 < valid)
            hout[(size_t)(n0 + e + 1) * HIDN + j] =
                __ldg(&h[(size_t)(n0 + e + 1) * HIDN + j]) + v.y;
    }
}

// ---------------------------------------------------------------------------
extern "C" void kernel_launch(void* const* d_in, const int* in_sizes, int n_in,
                              void* d_out, int out_size)
{
    const float* h   = (const float*)d_in[0];
    const float* x   = (const float*)d_in[1];
    const int*   ei  = (const int*)  d_in[2];
    const float* ea  = (const float*)d_in[3];
    const float* We1 = (const float*)d_in[4];
    const float* be1 = (const float*)d_in[5];
    const float* We2 = (const float*)d_in[6];
    const float* be2 = (const float*)d_in[7];
    const float* Wn1 = (const float*)d_in[8];
    const float* bn1 = (const float*)d_in[9];
    const float* Wn2 = (const float*)d_in[10];
    const float* bn2 = (const float*)d_in[11];
    const float* Wc1 = (const float*)d_in[12];
    const float* bc1 = (const float*)d_in[13];
    const float* Wc2 = (const float*)d_in[14];

    const int N = in_sizes[0] / HIDN;
    const int E = in_sizes[2] / 2;

    float* hout = (float*)d_out;
    float* xout = hout + (size_t)N * HIDN;

    float* mi = nullptr;
    cudaGetSymbolAddress((void**)&mi, g_mi);

    const int ESM = SMEM_WORDS * (int)sizeof(float);
    const int NSM = (2 * HIDN * PITCH) * (int)sizeof(float);
    cudaFuncSetAttribute(edge_kernel_mma, cudaFuncAttributeMaxDynamicSharedMemorySize, ESM);
    cudaFuncSetAttribute(node_kernel,     cudaFuncAttributeMaxDynamicSharedMemorySize, NSM);

    const int totmi = N * HIDN;
    init_kernel<<<(totmi + NTHREADS - 1) / NTHREADS, NTHREADS>>>(x, mi, xout, totmi, N * 3);
    edge_kernel_mma<<<(E + EM - 1) / EM, ETH, ESM>>>(h, x, ei, ea,
                                                     We1, be1, We2, be2,
                                                     Wc1, bc1, Wc2,
                                                     mi, xout, E);
    node_kernel<<<(N + TE - 1) / TE, NTHREADS, NSM>>>(h, mi, Wn1, bn1, Wn2, bn2, hout, N);
}

// round 5
// speedup vs baseline: 3.9364x; 1.6407x over previous
#include <cuda_runtime.h>
#include <cuda_fp16.h>

typedef unsigned int u32;
typedef unsigned long long u64;

#define HIDN 256
#define EDIM 64
#define MAXN 50000
#define MAXE 800000
#define EM   128
#define ETH  512
#define NC1  37            // GEMM1: K=577 padded to 592 = 37*16
#define NC2  16            // GEMM2/3: K=256

// smem byte offsets (edge kernel)
#define SO_BIAS 0          // 4*256 f32 = 4096B (be1,be2,bc1,wc2)
#define SO_S    4096       // 128 int
#define SO_D    4608       // 128 int
#define SO_REL  5120       // 384 f32
#define SO_CW   6656       // 128 f32
#define SO_A    8192       // 2 bufs * 128*12 u32 = 12288B
#define SO_B    20480      // 2 bufs * 2 planes * 256*12 u32 = 49152B
#define SO_M    69632      // persistent m plane: 128*132 u32 = 67584B
#define SMEM_EDGE 137216

// node kernel (fp32x2)
#define TE 32
#define NTHREADS 256
#define PITCH 34

// ---------------- device globals (prepacked data, no runtime alloc) ---------
__device__ u32 g_We1p[NC1 * 4096];          // [chunk][plane][n=256][kp=8] fp16x2
__device__ u32 g_We2p[NC2 * 4096];
__device__ u32 g_Wc1p[NC2 * 4096];
__device__ u32 g_hf[(size_t)MAXN * 128];    // h as fp16 pairs
__device__ u32 g_tail[(size_t)MAXE * 40];   // [dist, ea0..ea63, pad] fp16 pairs
__device__ float g_mi[(size_t)MAXN * HIDN];

// ---------------- helpers ----------------------------------------------------
__device__ __forceinline__ float silu_f(float v) {
    return v * (1.0f / (1.0f + __expf(-v)));
}
__device__ __forceinline__ u32 packh2(float a, float b) {
    __half2 h = __floats2half2_rn(a, b);
    return *(u32*)&h;
}
__device__ __forceinline__ void hsplit(float v, u32& hi, u32& lo) {
    __half h = __float2half_rn(v);
    __half l = __float2half_rn(v - __half2float(h));
    hi = (u32)__half_as_ushort(h);
    lo = (u32)__half_as_ushort(l);
}
__device__ __forceinline__ void mma_f16(float c[4], const u32 a[4], u32 b0, u32 b1) {
    asm volatile(
        "mma.sync.aligned.m16n8k16.row.col.f32.f16.f16.f32 "
        "{%0,%1,%2,%3}, {%4,%5,%6,%7}, {%8,%9}, {%0,%1,%2,%3};"
        : "+f"(c[0]), "+f"(c[1]), "+f"(c[2]), "+f"(c[3])
        : "r"(a[0]), "r"(a[1]), "r"(a[2]), "r"(a[3]), "r"(b0), "r"(b1));
}
__device__ __forceinline__ void red2(float* p, float a, float b) {
    asm volatile("red.global.add.v2.f32 [%0], {%1,%2};"
                 :: "l"(p), "f"(a), "f"(b) : "memory");
}

// ---------------- prep kernels -----------------------------------------------
__global__ void prep_weights(const float* __restrict__ We1,
                             const float* __restrict__ We2,
                             const float* __restrict__ Wc1)
{
    int i = blockIdx.x * blockDim.x + threadIdx.x;
    const int NW1 = NC1 * 2048, NW2 = NC2 * 2048;
    const float* W; u32* dst; int c, r, Kmax;
    if (i < NW1)                { W = We1; dst = g_We1p; c = i / 2048; r = i % 2048; Kmax = 577; }
    else if (i < NW1 + NW2)     { int j = i - NW1;       W = We2; dst = g_We2p; c = j / 2048; r = j % 2048; Kmax = 256; }
    else if (i < NW1 + 2 * NW2) { int j = i - NW1 - NW2; W = Wc1; dst = g_Wc1p; c = j / 2048; r = j % 2048; Kmax = 256; }
    else return;
    int n = r >> 3, kp = r & 7;
    int k = 16 * c + 2 * kp;
    float v0 = (k     < Kmax) ? W[(size_t)k * 256 + n]       : 0.f;
    float v1 = (k + 1 < Kmax) ? W[(size_t)(k + 1) * 256 + n] : 0.f;
    u32 h0, l0, h1, l1;
    hsplit(v0, h0, l0);
    hsplit(v1, h1, l1);
    dst[c * 4096 + n * 8 + kp]        = h0 | (h1 << 16);
    dst[c * 4096 + 2048 + n * 8 + kp] = l0 | (l1 << 16);
}

__global__ void prep_h(const float* __restrict__ h, int N)
{
    int i = blockIdx.x * blockDim.x + threadIdx.x;
    if (i >= N * 128) return;
    int node = i >> 7, kp = i & 127;
    const float* p = &h[(size_t)node * 256 + 2 * kp];
    g_hf[i] = packh2(p[0], p[1]);
}

__global__ void prep_tail(const float* __restrict__ x, const int* __restrict__ ei,
                          const float* __restrict__ ea, int E)
{
    int e = blockIdx.x * blockDim.x + threadIdx.x;
    if (e >= E) return;
    int s = ei[e], d = ei[E + e];
    float rx = x[3*s]   - x[3*d];
    float ry = x[3*s+1] - x[3*d+1];
    float rz = x[3*s+2] - x[3*d+2];
    float ds = rx*rx + ry*ry + rz*rz;
    u32* out = &g_tail[(size_t)e * 40];
    const float* a = &ea[(size_t)e * EDIM];
    out[0] = packh2(ds, a[0]);
    #pragma unroll
    for (int kp = 1; kp < 32; kp++) out[kp] = packh2(a[2*kp - 1], a[2*kp]);
    out[32] = packh2(a[63], 0.f);
    #pragma unroll
    for (int kp = 33; kp < 40; kp++) out[kp] = 0u;
}

__global__ void init_kernel(const float* __restrict__ x,
                            float* __restrict__ mi,
                            float* __restrict__ xout,
                            int total_mi, int total_x)
{
    int i = blockIdx.x * blockDim.x + threadIdx.x;
    if (i < total_mi) mi[i] = 0.0f;
    if (i < total_x)  xout[i] = x[i];
}

// ---------------- edge kernel ------------------------------------------------
__global__ void __launch_bounds__(ETH, 1)
edge_mma(const float* __restrict__ x, const int* __restrict__ ei,
         const float* __restrict__ be1, const float* __restrict__ be2,
         const float* __restrict__ bc1, const float* __restrict__ Wc2,
         float* __restrict__ mi, float* __restrict__ xout, int E)
{
    extern __shared__ char smem[];
    float* sBias = (float*)(smem + SO_BIAS);
    int*   sS    = (int*)(smem + SO_S);
    int*   sD    = (int*)(smem + SO_D);
    float* srel  = (float*)(smem + SO_REL);
    float* scw   = (float*)(smem + SO_CW);
    u32*   sA    = (u32*)(smem + SO_A);
    u32*   sB    = (u32*)(smem + SO_B);
    u32*   sM    = (u32*)(smem + SO_M);

    const int tid  = threadIdx.x;
    const int lane = tid & 31, wid = tid >> 5;
    const int wm = wid >> 2, wn = wid & 3;       // 4x4 warp grid
    const int g = lane >> 2, tig = lane & 3;
    const int e0 = blockIdx.x * EM;
    const int valid = min(EM, E - e0);

    if (tid < 256) {
        sBias[tid]       = __ldg(&be1[tid]);
        sBias[256 + tid] = __ldg(&be2[tid]);
        sBias[512 + tid] = __ldg(&bc1[tid]);
        sBias[768 + tid] = __ldg(&Wc2[tid]);
    }
    if (tid < EM) {
        int er = min(e0 + tid, E - 1);
        int s = ei[er], d = ei[E + er];
        float rx = x[3*s]   - x[3*d];
        float ry = x[3*s+1] - x[3*d+1];
        float rz = x[3*s+2] - x[3*d+2];
        sS[tid] = s; sD[tid] = d;
        srel[3*tid] = rx; srel[3*tid+1] = ry; srel[3*tid+2] = rz;
        scw[tid] = 0.f;
    }
    __syncthreads();

    float acc[16][4];
    uint4 ra, rb0, rb1;

    // --- staging: load to regs / commit to smem ---
    auto ldA1 = [&](int c) {
        if (tid < 256) {
            int row = tid >> 1, q = tid & 1;
            const u32* src;
            if (c < 16)      src = &g_hf[(size_t)sS[row] * 128 + 8*c + 4*q];
            else if (c < 32) src = &g_hf[(size_t)sD[row] * 128 + 8*(c-16) + 4*q];
            else {
                int er = min(e0 + row, E - 1);
                src = &g_tail[(size_t)er * 40 + 8*(c-32) + 4*q];
            }
            ra = *(const uint4*)src;
        }
    };
    auto stA1 = [&](int buf) {
        if (tid < 256) {
            int row = tid >> 1, q = tid & 1;
            *(uint4*)&sA[buf * 1536 + row * 12 + 4*q] = ra;
        }
    };
    auto ldB = [&](const u32* __restrict__ gW, int c) {
        int n = tid >> 1, q = tid & 1;
        rb0 = *(const uint4*)&gW[c * 4096 + n * 8 + 4*q];
        rb1 = *(const uint4*)&gW[c * 4096 + 2048 + n * 8 + 4*q];
    };
    auto stB = [&](int buf) {
        int n = tid >> 1, q = tid & 1;
        *(uint4*)&sB[buf * 6144 + n * 12 + 4*q]        = rb0;
        *(uint4*)&sB[buf * 6144 + 3072 + n * 12 + 4*q] = rb1;
    };
    auto zacc = [&]() {
        #pragma unroll
        for (int q = 0; q < 16; q++) {
            acc[q][0] = 0.f; acc[q][1] = 0.f; acc[q][2] = 0.f; acc[q][3] = 0.f;
        }
    };
    // 2-pass fp16 MMA over the warp's 32x64 tile for one k=16 chunk
    auto mma_chunk = [&](const u32* __restrict__ A, int astride, const u32* __restrict__ B) {
        u32 a[2][4];
        #pragma unroll
        for (int mt = 0; mt < 2; mt++) {
            int r = wm * 32 + mt * 16 + g;
            a[mt][0] = A[r * astride + tig];
            a[mt][1] = A[(r + 8) * astride + tig];
            a[mt][2] = A[r * astride + tig + 4];
            a[mt][3] = A[(r + 8) * astride + tig + 4];
        }
        #pragma unroll
        for (int nt = 0; nt < 8; nt++) {
            int n = wn * 64 + nt * 8 + g;
            u32 bh0 = B[n * 12 + tig],        bh1 = B[n * 12 + tig + 4];
            u32 bl0 = B[3072 + n * 12 + tig], bl1 = B[3072 + n * 12 + tig + 4];
            #pragma unroll
            for (int mt = 0; mt < 2; mt++) {
                mma_f16(acc[mt * 8 + nt], a[mt], bh0, bh1);
                mma_f16(acc[mt * 8 + nt], a[mt], bl0, bl1);
            }
        }
    };

    // ===== GEMM1: edge_input(128x592) @ We1 =====
    zacc();
    ldA1(0); ldB(g_We1p, 0);
    stA1(0); stB(0);
    __syncthreads();
    for (int c = 0; c < NC1; c++) {
        if (c + 1 < NC1) { ldA1(c + 1); ldB(g_We1p, c + 1); }
        mma_chunk(&sA[(c & 1) * 1536], 12, &sB[(c & 1) * 6144]);
        if (c + 1 < NC1) { stA1((c + 1) & 1); stB((c + 1) & 1); }
        __syncthreads();
    }
    // epilogue 1: m1 = silu(acc + be1) -> persistent fp16 plane sM
    #pragma unroll
    for (int mt = 0; mt < 2; mt++)
    #pragma unroll
    for (int nt = 0; nt < 8; nt++) {
        float* cc = acc[mt * 8 + nt];
        int c0 = wn * 64 + nt * 8 + 2 * tig, kp = c0 >> 1;
        int r0 = wm * 32 + mt * 16 + g;
        float b0 = sBias[c0], b1 = sBias[c0 + 1];
        sM[r0 * 132 + kp]       = packh2(silu_f(cc[0] + b0), silu_f(cc[1] + b1));
        sM[(r0 + 8) * 132 + kp] = packh2(silu_f(cc[2] + b0), silu_f(cc[3] + b1));
    }
    __syncthreads();

    // ===== GEMM2: m1 @ We2 (A direct from sM) =====
    zacc();
    ldB(g_We2p, 0); stB(0);
    __syncthreads();
    for (int c = 0; c < NC2; c++) {
        if (c + 1 < NC2) ldB(g_We2p, c + 1);
        mma_chunk(&sM[8 * c], 132, &sB[(c & 1) * 6144]);
        if (c + 1 < NC2) stB((c + 1) & 1);
        __syncthreads();
    }
    // epilogue 2: m_ij = silu(acc + be2) -> sM; scatter into g_mi[dst]
    #pragma unroll
    for (int mt = 0; mt < 2; mt++)
    #pragma unroll
    for (int nt = 0; nt < 8; nt++) {
        float* cc = acc[mt * 8 + nt];
        int c0 = wn * 64 + nt * 8 + 2 * tig, kp = c0 >> 1;
        int r0 = wm * 32 + mt * 16 + g;
        float b0 = sBias[256 + c0], b1 = sBias[256 + c0 + 1];
        float m00 = silu_f(cc[0] + b0), m01 = silu_f(cc[1] + b1);
        float m10 = silu_f(cc[2] + b0), m11 = silu_f(cc[3] + b1);
        sM[r0 * 132 + kp]       = packh2(m00, m01);
        sM[(r0 + 8) * 132 + kp] = packh2(m10, m11);
        if (r0 < valid)     red2(&mi[(size_t)sD[r0] * HIDN + c0], m00, m01);
        if (r0 + 8 < valid) red2(&mi[(size_t)sD[r0 + 8] * HIDN + c0], m10, m11);
    }
    __syncthreads();

    // ===== GEMM3: m_ij @ Wc1 =====
    zacc();
    ldB(g_Wc1p, 0); stB(0);
    __syncthreads();
    for (int c = 0; c < NC2; c++) {
        if (c + 1 < NC2) ldB(g_Wc1p, c + 1);
        mma_chunk(&sM[8 * c], 132, &sB[(c & 1) * 6144]);
        if (c + 1 < NC2) stB((c + 1) & 1);
        __syncthreads();
    }
    // epilogue 3: coord_w = sum_j silu(acc + bc1)_j * wc2_j, scatter xout
    {
        float rs[2][2] = {{0.f, 0.f}, {0.f, 0.f}};
        #pragma unroll
        for (int mt = 0; mt < 2; mt++)
        #pragma unroll
        for (int nt = 0; nt < 8; nt++) {
            float* cc = acc[mt * 8 + nt];
            int c0 = wn * 64 + nt * 8 + 2 * tig;
            float b0 = sBias[512 + c0], b1 = sBias[512 + c0 + 1];
            float w0 = sBias[768 + c0], w1 = sBias[768 + c0 + 1];
            rs[mt][0] += silu_f(cc[0] + b0) * w0 + silu_f(cc[1] + b1) * w1;
            rs[mt][1] += silu_f(cc[2] + b0) * w0 + silu_f(cc[3] + b1) * w1;
        }
        #pragma unroll
        for (int mt = 0; mt < 2; mt++)
        #pragma unroll
        for (int hh = 0; hh < 2; hh++) {
            float v = rs[mt][hh];
            v += __shfl_xor_sync(0xffffffffu, v, 1);
            v += __shfl_xor_sync(0xffffffffu, v, 2);
            rs[mt][hh] = v;
        }
        if (tig == 0) {
            atomicAdd(&scw[wm * 32 + g],      rs[0][0]);
            atomicAdd(&scw[wm * 32 + 8 + g],  rs[0][1]);
            atomicAdd(&scw[wm * 32 + 16 + g], rs[1][0]);
            atomicAdd(&scw[wm * 32 + 24 + g], rs[1][1]);
        }
    }
    __syncthreads();
    if (tid < EM && tid < valid) {
        int dn = sD[tid];
        float cw = scw[tid];
        atomicAdd(&xout[(size_t)dn * 3 + 0], srel[3*tid + 0] * cw);
        atomicAdd(&xout[(size_t)dn * 3 + 1], srel[3*tid + 1] * cw);
        atomicAdd(&xout[(size_t)dn * 3 + 2], srel[3*tid + 2] * cw);
    }
}

// ---------------- node kernel (fp32x2, unchanged) ----------------------------
__device__ __forceinline__ u64 splat2(float w) {
    u64 r; asm("mov.b64 %0, {%1, %1};" : "=l"(r) : "r"(__float_as_uint(w))); return r;
}
__device__ __forceinline__ u64 pack2(float a, float b) {
    u64 r; asm("mov.b64 %0, {%1, %2};" : "=l"(r) : "r"(__float_as_uint(a)), "r"(__float_as_uint(b))); return r;
}
__device__ __forceinline__ float2 unpack2(u64 v) {
    unsigned lo, hi; asm("mov.b64 {%0, %1}, %2;" : "=r"(lo), "=r"(hi) : "l"(v));
    return make_float2(__uint_as_float(lo), __uint_as_float(hi));
}
__device__ __forceinline__ void fma2(u64& a, u64 b, u64 c) {
    asm("fma.rn.f32x2 %0, %1, %2, %0;" : "+l"(a) : "l"(b), "l"(c));
}
template<int K>
__device__ __forceinline__ void gemm_core(u64 acc[16],
                                          const float* __restrict__ base,
                                          const float* __restrict__ W,
                                          int j, float bias)
{
    u64 b2 = splat2(bias);
    #pragma unroll
    for (int p = 0; p < 16; p++) acc[p] = b2;
    #pragma unroll 4
    for (int k = 0; k < K; k++) {
        u64 w2 = splat2(__ldg(&W[k * HIDN + j]));
        const u64* r2 = (const u64*)(base + (size_t)k * PITCH);
        #pragma unroll
        for (int p = 0; p < 16; p++) fma2(acc[p], r2[p], w2);
    }
}

__global__ void __launch_bounds__(NTHREADS, 2)
node_kernel(const float* __restrict__ h,   const float* __restrict__ mi,
            const float* __restrict__ Wn1, const float* __restrict__ bn1,
            const float* __restrict__ Wn2, const float* __restrict__ bn2,
            float* __restrict__ hout, int N)
{
    extern __shared__ float smn[];
    float* sA = smn;
    const int tid   = threadIdx.x;
    const int n0    = blockIdx.x * TE;
    const int valid = min(TE, N - n0);

    #pragma unroll 1
    for (int i = 0; i < TE; i++) {
        float a = 0.f, b = 0.f;
        if (i < valid) {
            a = __ldg(&h [(size_t)(n0 + i) * HIDN + tid]);
            b = __ldg(&mi[(size_t)(n0 + i) * HIDN + tid]);
        }
        sA[tid * PITCH + i]          = a;
        sA[(HIDN + tid) * PITCH + i] = b;
    }
    __syncthreads();

    const int j = tid;
    u64 acc[16];

    gemm_core<2 * HIDN>(acc, sA, Wn1, j, bn1[j]);
    __syncthreads();
    {
        u64* row = (u64*)(sA + (size_t)j * PITCH);
        #pragma unroll
        for (int p = 0; p < 16; p++) {
            float2 v = unpack2(acc[p]);
            row[p] = pack2(silu_f(v.x), silu_f(v.y));
        }
    }
    __syncthreads();

    gemm_core<HIDN>(acc, sA, Wn2, j, bn2[j]);

    #pragma unroll
    for (int p = 0; p < 16; p++) {
        float2 v = unpack2(acc[p]);
        int e = 2 * p;
        if (e < valid)
            hout[(size_t)(n0 + e) * HIDN + j] =
                __ldg(&h[(size_t)(n0 + e) * HIDN + j]) + v.x;
        if (e + 1 < valid)
            hout[(size_t)(n0 + e + 1) * HIDN + j] =
                __ldg(&h[(size_t)(n0 + e + 1) * HIDN + j]) + v.y;
    }
}

// ---------------------------------------------------------------------------
extern "C" void kernel_launch(void* const* d_in, const int* in_sizes, int n_in,
                              void* d_out, int out_size)
{
    const float* h   = (const float*)d_in[0];
    const float* x   = (const float*)d_in[1];
    const int*   ei  = (const int*)  d_in[2];
    const float* ea  = (const float*)d_in[3];
    const float* We1 = (const float*)d_in[4];
    const float* be1 = (const float*)d_in[5];
    const float* We2 = (const float*)d_in[6];
    const float* be2 = (const float*)d_in[7];
    const float* Wn1 = (const float*)d_in[8];
    const float* bn1 = (const float*)d_in[9];
    const float* Wn2 = (const float*)d_in[10];
    const float* bn2 = (const float*)d_in[11];
    const float* Wc1 = (const float*)d_in[12];
    const float* bc1 = (const float*)d_in[13];
    const float* Wc2 = (const float*)d_in[14];

    const int N = in_sizes[0] / HIDN;
    const int E = in_sizes[2] / 2;

    float* hout = (float*)d_out;
    float* xout = hout + (size_t)N * HIDN;

    float* mi = nullptr;
    cudaGetSymbolAddress((void**)&mi, g_mi);

    const int NSM = (2 * HIDN * PITCH) * (int)sizeof(float);
    cudaFuncSetAttribute(edge_mma,    cudaFuncAttributeMaxDynamicSharedMemorySize, SMEM_EDGE);
    cudaFuncSetAttribute(node_kernel, cudaFuncAttributeMaxDynamicSharedMemorySize, NSM);

    const int wItems = (NC1 + 2 * NC2) * 2048;
    prep_weights<<<(wItems + 255) / 256, 256>>>(We1, We2, Wc1);
    prep_h<<<(N * 128 + 255) / 256, 256>>>(h, N);
    prep_tail<<<(E + 255) / 256, 256>>>(x, ei, ea, E);

    const int totmi = N * HIDN;
    init_kernel<<<(totmi + NTHREADS - 1) / NTHREADS, NTHREADS>>>(x, mi, xout, totmi, N * 3);

    edge_mma<<<(E + EM - 1) / EM, ETH, SMEM_EDGE>>>(x, ei, be1, be2, bc1, Wc2,
                                                    mi, xout, E);
    node_kernel<<<(N + TE - 1) / TE, NTHREADS, NSM>>>(h, mi, Wn1, bn1, Wn2, bn2, hout, N);
}

// round 6
// speedup vs baseline: 4.0444x; 1.0274x over previous
#include <cuda_runtime.h>
#include <cuda_fp16.h>

typedef unsigned int u32;
typedef unsigned long long u64;

#define HIDN 256
#define EDIM 64
#define MAXN 50000
#define MAXE 800000
#define EM   128
#define ETH  512
#define NC1  37            // GEMM1: K=577 padded to 592 = 37*16
#define NC2  16            // GEMM2/3: K=256
#define NS1  19            // GEMM1 stages (2 chunks/stage, last has 1)
#define NS2  8             // GEMM2/3 stages

// smem (bytes). A: 2 bufs * 2 ch * 1536 u32 ; B: 2 bufs * 2 ch * 6144 u32 ; M: 128*132 u32
#define SO_BIAS 0
#define SO_S    4096
#define SO_D    4608
#define SO_REL  5120
#define SO_CW   6656
#define SO_A    8192
#define SO_B    32768
#define SO_M    131072
#define SMEM_EDGE 198656

// node kernel (fp32x2)
#define TE 32
#define NTHREADS 256
#define PITCH 34

// ---------------- device globals ---------------------------------------------
__device__ u32 g_We1p[NC1 * 4096];          // [chunk][plane][n][kp] fp16x2
__device__ u32 g_We2p[NC2 * 4096];
__device__ u32 g_Wc1p[NC2 * 4096];
__device__ u32 g_hf[(size_t)MAXN * 128];    // h as fp16 pairs
__device__ u32 g_tail[(size_t)MAXE * 40];   // [dist, ea0..63, pad] fp16 pairs
__device__ float g_mi[(size_t)MAXN * HIDN];

// ---------------- helpers -----------------------------------------------------
__device__ __forceinline__ float silu_f(float v) {
    return v * (1.0f / (1.0f + __expf(-v)));
}
__device__ __forceinline__ u32 packh2(float a, float b) {
    __half2 h = __floats2half2_rn(a, b);
    return *(u32*)&h;
}
__device__ __forceinline__ void hsplit(float v, u32& hi, u32& lo) {
    __half h = __float2half_rn(v);
    __half l = __float2half_rn(v - __half2float(h));
    hi = (u32)__half_as_ushort(h);
    lo = (u32)__half_as_ushort(l);
}
__device__ __forceinline__ void mma_f16(float c[4], const u32 a[4], u32 b0, u32 b1) {
    asm volatile(
        "mma.sync.aligned.m16n8k16.row.col.f32.f16.f16.f32 "
        "{%0,%1,%2,%3}, {%4,%5,%6,%7}, {%8,%9}, {%0,%1,%2,%3};"
        : "+f"(c[0]), "+f"(c[1]), "+f"(c[2]), "+f"(c[3])
        : "r"(a[0]), "r"(a[1]), "r"(a[2]), "r"(a[3]), "r"(b0), "r"(b1));
}
__device__ __forceinline__ void ldsm4(u32 r[4], u32 addr) {
    asm volatile("ldmatrix.sync.aligned.m8n8.x4.shared.b16 {%0,%1,%2,%3}, [%4];"
                 : "=r"(r[0]), "=r"(r[1]), "=r"(r[2]), "=r"(r[3]) : "r"(addr));
}
__device__ __forceinline__ u32 cvta_s(const void* p) {
    return (u32)__cvta_generic_to_shared(p);
}
__device__ __forceinline__ void red2(float* p, float a, float b) {
    asm volatile("red.global.add.v2.f32 [%0], {%1,%2};"
                 :: "l"(p), "f"(a), "f"(b) : "memory");
}

// 2-pass fp16 MMA over warp's 32x64 tile for one k=16 chunk, ldmatrix fragments.
// B: plane hi at +0, plane lo at +3072 u32, row pitch 12 u32.
__device__ __forceinline__ void do_chunk(float (*acc)[4],
    const u32* __restrict__ A, int astride, const u32* __restrict__ B,
    int wm, int wn, int lane)
{
    const int sel = lane >> 3, lrow = lane & 7;
    u32 a0[4], a1[4];
    {
        u32 ab = cvta_s(A) + (((u32)(wm * 32 + (sel & 1) * 8 + lrow) * astride
                               + (u32)(sel >> 1) * 4) << 2);
        ldsm4(a0, ab);
        ldsm4(a1, ab + ((u32)astride << 6));   // +16 rows
    }
    const u32 bb = cvta_s(B);
    #pragma unroll
    for (int ntp = 0; ntp < 4; ntp++) {
        u32 boff = (((u32)(wn * 64 + ntp * 16 + (sel >> 1) * 8 + lrow) * 12
                     + (u32)(sel & 1) * 4) << 2);
        u32 bh[4], bl[4];
        ldsm4(bh, bb + boff);
        ldsm4(bl, bb + 12288 + boff);          // lo plane (+3072 u32)
        #pragma unroll
        for (int sub = 0; sub < 2; sub++) {
            int nt = 2 * ntp + sub;
            mma_f16(acc[nt],     a0, bh[2*sub], bh[2*sub+1]);
            mma_f16(acc[nt],     a0, bl[2*sub], bl[2*sub+1]);
            mma_f16(acc[8 + nt], a1, bh[2*sub], bh[2*sub+1]);
            mma_f16(acc[8 + nt], a1, bl[2*sub], bl[2*sub+1]);
        }
    }
}

// ---------------- prep kernels -------------------------------------------------
__global__ void prep_weights(const float* __restrict__ We1,
                             const float* __restrict__ We2,
                             const float* __restrict__ Wc1)
{
    int i = blockIdx.x * blockDim.x + threadIdx.x;
    const int NW1 = NC1 * 2048, NW2 = NC2 * 2048;
    const float* W; u32* dst; int c, r, Kmax;
    if (i < NW1)                { W = We1; dst = g_We1p; c = i / 2048; r = i % 2048; Kmax = 577; }
    else if (i < NW1 + NW2)     { int j = i - NW1;       W = We2; dst = g_We2p; c = j / 2048; r = j % 2048; Kmax = 256; }
    else if (i < NW1 + 2 * NW2) { int j = i - NW1 - NW2; W = Wc1; dst = g_Wc1p; c = j / 2048; r = j % 2048; Kmax = 256; }
    else return;
    int n = r >> 3, kp = r & 7;
    int k = 16 * c + 2 * kp;
    float v0 = (k     < Kmax) ? W[(size_t)k * 256 + n]       : 0.f;
    float v1 = (k + 1 < Kmax) ? W[(size_t)(k + 1) * 256 + n] : 0.f;
    u32 h0, l0, h1, l1;
    hsplit(v0, h0, l0);
    hsplit(v1, h1, l1);
    dst[c * 4096 + n * 8 + kp]        = h0 | (h1 << 16);
    dst[c * 4096 + 2048 + n * 8 + kp] = l0 | (l1 << 16);
}

__global__ void prep_h(const float* __restrict__ h, int N)
{
    int i = blockIdx.x * blockDim.x + threadIdx.x;
    if (i >= N * 128) return;
    int node = i >> 7, kp = i & 127;
    const float* p = &h[(size_t)node * 256 + 2 * kp];
    g_hf[i] = packh2(p[0], p[1]);
}

__global__ void prep_tail(const float* __restrict__ x, const int* __restrict__ ei,
                          const float* __restrict__ ea, int E)
{
    int e = blockIdx.x * blockDim.x + threadIdx.x;
    if (e >= E) return;
    int s = ei[e], d = ei[E + e];
    float rx = x[3*s]   - x[3*d];
    float ry = x[3*s+1] - x[3*d+1];
    float rz = x[3*s+2] - x[3*d+2];
    float ds = rx*rx + ry*ry + rz*rz;
    u32* out = &g_tail[(size_t)e * 40];
    const float* a = &ea[(size_t)e * EDIM];
    out[0] = packh2(ds, a[0]);
    #pragma unroll
    for (int kp = 1; kp < 32; kp++) out[kp] = packh2(a[2*kp - 1], a[2*kp]);
    out[32] = packh2(a[63], 0.f);
    #pragma unroll
    for (int kp = 33; kp < 40; kp++) out[kp] = 0u;
}

__global__ void init_kernel(const float* __restrict__ x,
                            float* __restrict__ mi,
                            float* __restrict__ xout,
                            int total_mi, int total_x)
{
    int i = blockIdx.x * blockDim.x + threadIdx.x;
    if (i < total_mi) mi[i] = 0.0f;
    if (i < total_x)  xout[i] = x[i];
}

// ---------------- edge kernel ---------------------------------------------------
__global__ void __launch_bounds__(ETH, 1)
edge_mma(const float* __restrict__ x, const int* __restrict__ ei,
         const float* __restrict__ be1, const float* __restrict__ be2,
         const float* __restrict__ bc1, const float* __restrict__ Wc2,
         float* __restrict__ mi, float* __restrict__ xout, int E)
{
    extern __shared__ char smem[];
    float* sBias = (float*)(smem + SO_BIAS);
    int*   sS    = (int*)(smem + SO_S);
    int*   sD    = (int*)(smem + SO_D);
    float* srel  = (float*)(smem + SO_REL);
    float* scw   = (float*)(smem + SO_CW);
    u32*   sA    = (u32*)(smem + SO_A);
    u32*   sB    = (u32*)(smem + SO_B);
    u32*   sM    = (u32*)(smem + SO_M);

    const int tid  = threadIdx.x;
    const int lane = tid & 31, wid = tid >> 5;
    const int wm = wid >> 2, wn = wid & 3;
    const int g = lane >> 2, tig = lane & 3;
    const int e0 = blockIdx.x * EM;
    const int valid = min(EM, E - e0);

    if (tid < 256) {
        sBias[tid]       = __ldg(&be1[tid]);
        sBias[256 + tid] = __ldg(&be2[tid]);
        sBias[512 + tid] = __ldg(&bc1[tid]);
        sBias[768 + tid] = __ldg(&Wc2[tid]);
    }
    if (tid < EM) {
        int er = min(e0 + tid, E - 1);
        int s = ei[er], d = ei[E + er];
        float rx = x[3*s]   - x[3*d];
        float ry = x[3*s+1] - x[3*d+1];
        float rz = x[3*s+2] - x[3*d+2];
        sS[tid] = s; sD[tid] = d;
        srel[3*tid] = rx; srel[3*tid+1] = ry; srel[3*tid+2] = rz;
        scw[tid] = 0.f;
    }
    __syncthreads();

    float acc[16][4];
    uint4 ra;
    uint4 rb[4];

    // ---- stage loaders (2 chunks per stage) ----
    auto ldA_stage = [&](int s) {
        int ch = tid >> 8, r = tid & 255;
        int row = r >> 1, q = r & 1;
        int c = 2 * s + ch;
        if (c < NC1) {
            const u32* src;
            if (c < 16)      src = &g_hf[(size_t)sS[row] * 128 + 8*c + 4*q];
            else if (c < 32) src = &g_hf[(size_t)sD[row] * 128 + 8*(c-16) + 4*q];
            else {
                int er = min(e0 + row, E - 1);
                src = &g_tail[(size_t)er * 40 + 8*(c-32) + 4*q];
            }
            ra = *(const uint4*)src;
        } else ra = make_uint4(0u, 0u, 0u, 0u);
    };
    auto stA_stage = [&](int buf) {
        int ch = tid >> 8, r = tid & 255;
        int row = r >> 1, q = r & 1;
        *(uint4*)&sA[buf * 3072 + ch * 1536 + row * 12 + 4*q] = ra;
    };
    auto ldB_stage = [&](const u32* __restrict__ gW, int s, int nc) {
        int n = tid >> 1, q = tid & 1;
        int c0 = 2 * s, c1 = 2 * s + 1;
        rb[0] = *(const uint4*)&gW[c0 * 4096 + n * 8 + 4*q];
        rb[1] = *(const uint4*)&gW[c0 * 4096 + 2048 + n * 8 + 4*q];
        if (c1 < nc) {
            rb[2] = *(const uint4*)&gW[c1 * 4096 + n * 8 + 4*q];
            rb[3] = *(const uint4*)&gW[c1 * 4096 + 2048 + n * 8 + 4*q];
        } else {
            rb[2] = make_uint4(0u,0u,0u,0u);
            rb[3] = make_uint4(0u,0u,0u,0u);
        }
    };
    auto stB_stage = [&](int buf) {
        int n = tid >> 1, q = tid & 1;
        u32 base = buf * 12288;
        *(uint4*)&sB[base + n * 12 + 4*q]               = rb[0];
        *(uint4*)&sB[base + 3072 + n * 12 + 4*q]        = rb[1];
        *(uint4*)&sB[base + 6144 + n * 12 + 4*q]        = rb[2];
        *(uint4*)&sB[base + 6144 + 3072 + n * 12 + 4*q] = rb[3];
    };
    auto zacc = [&]() {
        #pragma unroll
        for (int q = 0; q < 16; q++) {
            acc[q][0] = 0.f; acc[q][1] = 0.f; acc[q][2] = 0.f; acc[q][3] = 0.f;
        }
    };

    // ===== GEMM1: edge_input(128x592) @ We1 =====
    zacc();
    ldA_stage(0); ldB_stage(g_We1p, 0, NC1);
    stA_stage(0); stB_stage(0);
    __syncthreads();
    for (int s = 0; s < NS1; s++) {
        if (s + 1 < NS1) { ldA_stage(s + 1); ldB_stage(g_We1p, s + 1, NC1); }
        const u32* Ab = &sA[(s & 1) * 3072];
        const u32* Bb = &sB[(s & 1) * 12288];
        do_chunk(acc, Ab, 12, Bb, wm, wn, lane);
        if (2 * s + 1 < NC1) do_chunk(acc, Ab + 1536, 12, Bb + 6144, wm, wn, lane);
        if (s + 1 < NS1) { stA_stage((s + 1) & 1); stB_stage((s + 1) & 1); }
        __syncthreads();
    }
    // epilogue 1: m1 = silu(acc + be1) -> persistent fp16 plane sM
    #pragma unroll
    for (int mt = 0; mt < 2; mt++)
    #pragma unroll
    for (int nt = 0; nt < 8; nt++) {
        float* cc = acc[mt * 8 + nt];
        int c0 = wn * 64 + nt * 8 + 2 * tig, kp = c0 >> 1;
        int r0 = wm * 32 + mt * 16 + g;
        float b0 = sBias[c0], b1 = sBias[c0 + 1];
        sM[r0 * 132 + kp]       = packh2(silu_f(cc[0] + b0), silu_f(cc[1] + b1));
        sM[(r0 + 8) * 132 + kp] = packh2(silu_f(cc[2] + b0), silu_f(cc[3] + b1));
    }
    __syncthreads();

    // ===== GEMM2: m1 @ We2 (A direct from sM) =====
    zacc();
    ldB_stage(g_We2p, 0, NC2); stB_stage(0);
    __syncthreads();
    for (int s = 0; s < NS2; s++) {
        if (s + 1 < NS2) ldB_stage(g_We2p, s + 1, NC2);
        const u32* Bb = &sB[(s & 1) * 12288];
        do_chunk(acc, &sM[8 * (2 * s)],     132, Bb,        wm, wn, lane);
        do_chunk(acc, &sM[8 * (2 * s + 1)], 132, Bb + 6144, wm, wn, lane);
        if (s + 1 < NS2) stB_stage((s + 1) & 1);
        __syncthreads();
    }
    // epilogue 2: m_ij = silu(acc + be2) -> sM; scatter into g_mi[dst]
    #pragma unroll
    for (int mt = 0; mt < 2; mt++)
    #pragma unroll
    for (int nt = 0; nt < 8; nt++) {
        float* cc = acc[mt * 8 + nt];
        int c0 = wn * 64 + nt * 8 + 2 * tig, kp = c0 >> 1;
        int r0 = wm * 32 + mt * 16 + g;
        float b0 = sBias[256 + c0], b1 = sBias[256 + c0 + 1];
        float m00 = silu_f(cc[0] + b0), m01 = silu_f(cc[1] + b1);
        float m10 = silu_f(cc[2] + b0), m11 = silu_f(cc[3] + b1);
        sM[r0 * 132 + kp]       = packh2(m00, m01);
        sM[(r0 + 8) * 132 + kp] = packh2(m10, m11);
        if (r0 < valid)     red2(&mi[(size_t)sD[r0] * HIDN + c0], m00, m01);
        if (r0 + 8 < valid) red2(&mi[(size_t)sD[r0 + 8] * HIDN + c0], m10, m11);
    }
    __syncthreads();

    // ===== GEMM3: m_ij @ Wc1 =====
    zacc();
    ldB_stage(g_Wc1p, 0, NC2); stB_stage(0);
    __syncthreads();
    for (int s = 0; s < NS2; s++) {
        if (s + 1 < NS2) ldB_stage(g_Wc1p, s + 1, NC2);
        const u32* Bb = &sB[(s & 1) * 12288];
        do_chunk(acc, &sM[8 * (2 * s)],     132, Bb,        wm, wn, lane);
        do_chunk(acc, &sM[8 * (2 * s + 1)], 132, Bb + 6144, wm, wn, lane);
        if (s + 1 < NS2) stB_stage((s + 1) & 1);
        __syncthreads();
    }
    // epilogue 3: coord_w = sum_j silu(acc + bc1)_j * wc2_j, scatter xout
    {
        float rs[2][2] = {{0.f, 0.f}, {0.f, 0.f}};
        #pragma unroll
        for (int mt = 0; mt < 2; mt++)
        #pragma unroll
        for (int nt = 0; nt < 8; nt++) {
            float* cc = acc[mt * 8 + nt];
            int c0 = wn * 64 + nt * 8 + 2 * tig;
            float b0 = sBias[512 + c0], b1 = sBias[512 + c0 + 1];
            float w0 = sBias[768 + c0], w1 = sBias[768 + c0 + 1];
            rs[mt][0] += silu_f(cc[0] + b0) * w0 + silu_f(cc[1] + b1) * w1;
            rs[mt][1] += silu_f(cc[2] + b0) * w0 + silu_f(cc[3] + b1) * w1;
        }
        #pragma unroll
        for (int mt = 0; mt < 2; mt++)
        #pragma unroll
        for (int hh = 0; hh < 2; hh++) {
            float v = rs[mt][hh];
            v += __shfl_xor_sync(0xffffffffu, v, 1);
            v += __shfl_xor_sync(0xffffffffu, v, 2);
            rs[mt][hh] = v;
        }
        if (tig == 0) {
            atomicAdd(&scw[wm * 32 + g],      rs[0][0]);
            atomicAdd(&scw[wm * 32 + 8 + g],  rs[0][1]);
            atomicAdd(&scw[wm * 32 + 16 + g], rs[1][0]);
            atomicAdd(&scw[wm * 32 + 24 + g], rs[1][1]);
        }
    }
    __syncthreads();
    if (tid < EM && tid < valid) {
        int dn = sD[tid];
        float cw = scw[tid];
        atomicAdd(&xout[(size_t)dn * 3 + 0], srel[3*tid + 0] * cw);
        atomicAdd(&xout[(size_t)dn * 3 + 1], srel[3*tid + 1] * cw);
        atomicAdd(&xout[(size_t)dn * 3 + 2], srel[3*tid + 2] * cw);
    }
}

// ---------------- node kernel (fp32x2, unchanged) -------------------------------
__device__ __forceinline__ u64 splat2(float w) {
    u64 r; asm("mov.b64 %0, {%1, %1};" : "=l"(r) : "r"(__float_as_uint(w))); return r;
}
__device__ __forceinline__ u64 pack2(float a, float b) {
    u64 r; asm("mov.b64 %0, {%1, %2};" : "=l"(r) : "r"(__float_as_uint(a)), "r"(__float_as_uint(b))); return r;
}
__device__ __forceinline__ float2 unpack2(u64 v) {
    unsigned lo, hi; asm("mov.b64 {%0, %1}, %2;" : "=r"(lo), "=r"(hi) : "l"(v));
    return make_float2(__uint_as_float(lo), __uint_as_float(hi));
}
__device__ __forceinline__ void fma2(u64& a, u64 b, u64 c) {
    asm("fma.rn.f32x2 %0, %1, %2, %0;" : "+l"(a) : "l"(b), "l"(c));
}
template<int K>
__device__ __forceinline__ void gemm_core(u64 acc[16],
                                          const float* __restrict__ base,
                                          const float* __restrict__ W,
                                          int j, float bias)
{
    u64 b2 = splat2(bias);
    #pragma unroll
    for (int p = 0; p < 16; p++) acc[p] = b2;
    #pragma unroll 4
    for (int k = 0; k < K; k++) {
        u64 w2 = splat2(__ldg(&W[k * HIDN + j]));
        const u64* r2 = (const u64*)(base + (size_t)k * PITCH);
        #pragma unroll
        for (int p = 0; p < 16; p++) fma2(acc[p], r2[p], w2);
    }
}

__global__ void __launch_bounds__(NTHREADS, 2)
node_kernel(const float* __restrict__ h,   const float* __restrict__ mi,
            const float* __restrict__ Wn1, const float* __restrict__ bn1,
            const float* __restrict__ Wn2, const float* __restrict__ bn2,
            float* __restrict__ hout, int N)
{
    extern __shared__ float smn[];
    float* sA = smn;
    const int tid   = threadIdx.x;
    const int n0    = blockIdx.x * TE;
    const int valid = min(TE, N - n0);

    #pragma unroll 1
    for (int i = 0; i < TE; i++) {
        float a = 0.f, b = 0.f;
        if (i < valid) {
            a = __ldg(&h [(size_t)(n0 + i) * HIDN + tid]);
            b = __ldg(&mi[(size_t)(n0 + i) * HIDN + tid]);
        }
        sA[tid * PITCH + i]          = a;
        sA[(HIDN + tid) * PITCH + i] = b;
    }
    __syncthreads();

    const int j = tid;
    u64 acc[16];

    gemm_core<2 * HIDN>(acc, sA, Wn1, j, bn1[j]);
    __syncthreads();
    {
        u64* row = (u64*)(sA + (size_t)j * PITCH);
        #pragma unroll
        for (int p = 0; p < 16; p++) {
            float2 v = unpack2(acc[p]);
            row[p] = pack2(silu_f(v.x), silu_f(v.y));
        }
    }
    __syncthreads();

    gemm_core<HIDN>(acc, sA, Wn2, j, bn2[j]);

    #pragma unroll
    for (int p = 0; p < 16; p++) {
        float2 v = unpack2(acc[p]);
        int e = 2 * p;
        if (e < valid)
            hout[(size_t)(n0 + e) * HIDN + j] =
                __ldg(&h[(size_t)(n0 + e) * HIDN + j]) + v.x;
        if (e + 1 < valid)
            hout[(size_t)(n0 + e + 1) * HIDN + j] =
                __ldg(&h[(size_t)(n0 + e + 1) * HIDN + j]) + v.y;
    }
}

// ---------------------------------------------------------------------------
extern "C" void kernel_launch(void* const* d_in, const int* in_sizes, int n_in,
                              void* d_out, int out_size)
{
    const float* h   = (const float*)d_in[0];
    const float* x   = (const float*)d_in[1];
    const int*   ei  = (const int*)  d_in[2];
    const float* ea  = (const float*)d_in[3];
    const float* We1 = (const float*)d_in[4];
    const float* be1 = (const float*)d_in[5];
    const float* We2 = (const float*)d_in[6];
    const float* be2 = (const float*)d_in[7];
    const float* Wn1 = (const float*)d_in[8];
    const float* bn1 = (const float*)d_in[9];
    const float* Wn2 = (const float*)d_in[10];
    const float* bn2 = (const float*)d_in[11];
    const float* Wc1 = (const float*)d_in[12];
    const float* bc1 = (const float*)d_in[13];
    const float* Wc2 = (const float*)d_in[14];

    const int N = in_sizes[0] / HIDN;
    const int E = in_sizes[2] / 2;

    float* hout = (float*)d_out;
    float* xout = hout + (size_t)N * HIDN;

    float* mi = nullptr;
    cudaGetSymbolAddress((void**)&mi, g_mi);

    const int NSM = (2 * HIDN * PITCH) * (int)sizeof(float);
    cudaFuncSetAttribute(edge_mma,    cudaFuncAttributeMaxDynamicSharedMemorySize, SMEM_EDGE);
    cudaFuncSetAttribute(node_kernel, cudaFuncAttributeMaxDynamicSharedMemorySize, NSM);

    const int wItems = (NC1 + 2 * NC2) * 2048;
    prep_weights<<<(wItems + 255) / 256, 256>>>(We1, We2, Wc1);
    prep_h<<<(N * 128 + 255) / 256, 256>>>(h, N);
    prep_tail<<<(E + 255) / 256, 256>>>(x, ei, ea, E);

    const int totmi = N * HIDN;
    init_kernel<<<(totmi + NTHREADS - 1) / NTHREADS, NTHREADS>>>(x, mi, xout, totmi, N * 3);

    edge_mma<<<(E + EM - 1) / EM, ETH, SMEM_EDGE>>>(x, ei, be1, be2, bc1, Wc2,
                                                    mi, xout, E);
    node_kernel<<<(N + TE - 1) / TE, NTHREADS, NSM>>>(h, mi, Wn1, bn1, Wn2, bn2, hout, N);
}